// round 13
// baseline (speedup 1.0000x reference)
#include <cuda_runtime.h>

#define NB    32768
#define QK    4096
#define NBLK1 1024
#define XSTR  20
#define ESTR  68
#define NCHUNK 16
#define PPERCH (NBLK1 / NCHUNK)

typedef unsigned long long u64;

__device__ float g_M[256];
__device__ float g_pm[(size_t)NBLK1 * QK];
__device__ float g_ps[(size_t)NBLK1 * QK];
__device__ float g_pm2[(size_t)NCHUNK * QK];
__device__ float g_ps2[(size_t)NCHUNK * QK];
__device__ float g_moff[QK];
__device__ float g_s[(size_t)NB * QK];    // scores, linear [b][q*64+k]
__device__ float g_u[(size_t)NB * 1024];

// ---- packed fp32x2 helpers ----
__device__ __forceinline__ void fma2(u64 &acc, u64 a, u64 b) {
    asm("fma.rn.f32x2 %0, %1, %2, %0;" : "+l"(acc) : "l"(a), "l"(b));
}
__device__ __forceinline__ u64 pack2(float x) {
    u64 r; asm("mov.b64 %0, {%1, %1};" : "=l"(r) : "f"(x)); return r;
}
__device__ __forceinline__ u64 pack2b(float x, float y) {
    u64 r; asm("mov.b64 %0, {%1, %2};" : "=l"(r) : "f"(x), "f"(y)); return r;
}
__device__ __forceinline__ float2 unpack2(u64 a) {
    float2 f; asm("mov.b64 {%0, %1}, %2;" : "=f"(f.x), "=f"(f.y) : "l"(a)); return f;
}

// -------- k0: M = Wq @ Wk^T / 3   (verbatim R12)
__global__ void k0_prep(const float* __restrict__ Wq, const float* __restrict__ Wk) {
    int t = threadIdx.x, i = t >> 4, j = t & 15;
    float a = 0.f;
#pragma unroll
    for (int o = 0; o < 16; ++o) a += Wq[i * 16 + o] * Wk[j * 16 + o];
    g_M[t] = a * (1.0f / 3.0f);
}

// -------- k1: R12 structure, but M in smem + __launch_bounds__(256,2)
//          to cut register pressure and double occupancy
__global__ __launch_bounds__(256, 2) void k1_maxsum(const float* __restrict__ x) {
    __shared__ __align__(16) float xs[2][64 * XSTR];
    __shared__ __align__(16) float ts[2][64 * XSTR];
    __shared__ __align__(16) float Ms[256];
    const int tid = threadIdx.x;
    const int ty = tid >> 4, tx = tid & 15;
    const int tq = tid >> 2, tc4 = (tid & 3) << 2;
    const int base = (tid & 31) & ~3;

    Ms[tid] = g_M[tid];

    float rm[16], rs[16];
#pragma unroll
    for (int j = 0; j < 16; ++j) { rm[j] = -1e30f; rs[j] = 0.f; }

    float4 pre = *reinterpret_cast<const float4*>(&x[(size_t)blockIdx.x * 1024 + tid * 4]);
    __syncthreads();   // Ms visible before first t-compute

    for (int it = 0; it < NB / NBLK1; ++it) {
        const int buf = it & 1;
        const int b = blockIdx.x + it * NBLK1;
        *reinterpret_cast<float4*>(&xs[buf][tq * XSTR + tc4]) = pre;
        float xrow[16];
#pragma unroll
        for (int c = 0; c < 4; ++c) {
            xrow[c * 4 + 0] = __shfl_sync(0xffffffffu, pre.x, base + c);
            xrow[c * 4 + 1] = __shfl_sync(0xffffffffu, pre.y, base + c);
            xrow[c * 4 + 2] = __shfl_sync(0xffffffffu, pre.z, base + c);
            xrow[c * 4 + 3] = __shfl_sync(0xffffffffu, pre.w, base + c);
        }
        {
            u64 t0 = 0, t1 = 0;
#pragma unroll
            for (int d = 0; d < 16; ++d) {
                u64 xp = pack2(xrow[d]);
                ulonglong2 mm = *reinterpret_cast<const ulonglong2*>(&Ms[d * 16 + tc4]);
                fma2(t0, xp, mm.x); fma2(t1, xp, mm.y);
            }
            ulonglong2 tv; tv.x = t0; tv.y = t1;
            *reinterpret_cast<ulonglong2*>(&ts[buf][tq * XSTR + tc4]) = tv;
        }
        if (it + 1 < NB / NBLK1)
            pre = *reinterpret_cast<const float4*>(
                &x[(size_t)(blockIdx.x + (it + 1) * NBLK1) * 1024 + tid * 4]);
        __syncthreads();
        u64 acc[16];
#pragma unroll
        for (int j = 0; j < 16; ++j) acc[j] = 0ull;
#pragma unroll
        for (int d4 = 0; d4 < 4; ++d4) {
            ulonglong2 a[4], bb[4];
#pragma unroll
            for (int r = 0; r < 4; ++r)
                a[r] = *reinterpret_cast<const ulonglong2*>(&ts[buf][(ty + 16 * r) * XSTR + d4 * 4]);
#pragma unroll
            for (int c = 0; c < 4; ++c)
                bb[c] = *reinterpret_cast<const ulonglong2*>(&xs[buf][(4 * tx + c) * XSTR + d4 * 4]);
#pragma unroll
            for (int r = 0; r < 4; ++r)
#pragma unroll
                for (int c = 0; c < 4; ++c) {
                    fma2(acc[r * 4 + c], a[r].x, bb[c].x);
                    fma2(acc[r * 4 + c], a[r].y, bb[c].y);
                }
        }
        float sv[16];
#pragma unroll
        for (int j = 0; j < 16; ++j) {
            float2 p2 = unpack2(acc[j]);
            sv[j] = p2.x + p2.y;
        }
#pragma unroll
        for (int j = 0; j < 16; ++j) {
            float v = sv[j];
            float d = v - rm[j];
            float e = __expf(fminf(d, -d));
            rs[j] = (d > 0.f) ? fmaf(rs[j], e, 1.f) : (rs[j] + e);
            rm[j] = fmaxf(rm[j], v);
        }
        float* sb = g_s + (size_t)b * QK;
#pragma unroll
        for (int r = 0; r < 4; ++r)
            *reinterpret_cast<float4*>(&sb[(ty + 16 * r) * 64 + 4 * tx]) =
                make_float4(sv[r * 4 + 0], sv[r * 4 + 1], sv[r * 4 + 2], sv[r * 4 + 3]);
    }
#pragma unroll
    for (int j = 0; j < 16; ++j) {
        int q = ty + 16 * (j >> 2), k = 4 * tx + (j & 3);
        g_pm[(size_t)blockIdx.x * QK + q * 64 + k] = rm[j];
        g_ps[(size_t)blockIdx.x * QK + q * 64 + k] = rs[j];
    }
}

// -------- k2a   (verbatim R12)
__global__ __launch_bounds__(256) void k2a_reduce(void) {
    const int posblk = blockIdx.x & 15;
    const int pchunk = blockIdx.x >> 4;
    const int pos = posblk * 256 + threadIdx.x;
    const int p0 = pchunk * PPERCH;

    float m = -1e30f, S = 0.f;
#pragma unroll 1
    for (int pp = 0; pp < PPERCH; pp += 4) {
        float ml[4], sl[4];
#pragma unroll
        for (int i = 0; i < 4; ++i) {
            ml[i] = g_pm[(size_t)(p0 + pp + i) * QK + pos];
            sl[i] = g_ps[(size_t)(p0 + pp + i) * QK + pos];
        }
#pragma unroll
        for (int i = 0; i < 4; ++i) {
            if (ml[i] > m) { S = fmaf(S, __expf(m - ml[i]), sl[i]); m = ml[i]; }
            else           { S = fmaf(sl[i], __expf(ml[i] - m), S); }
        }
    }
    g_pm2[(size_t)pchunk * QK + pos] = m;
    g_ps2[(size_t)pchunk * QK + pos] = S;
}

// -------- k2b   (verbatim R12)
__global__ __launch_bounds__(256) void k2b_reduce(void) {
    const int pos = blockIdx.x * 256 + threadIdx.x;
    float m = -1e30f, S = 0.f;
#pragma unroll
    for (int c = 0; c < NCHUNK; ++c) {
        float mc = g_pm2[(size_t)c * QK + pos];
        float sc = g_ps2[(size_t)c * QK + pos];
        if (mc > m) { S = fmaf(S, __expf(m - mc), sc); m = mc; }
        else        { S = fmaf(sc, __expf(mc - m), S); }
    }
    g_moff[pos] = m + __logf(S);
}

// -------- k3   (verbatim R12: prefetch of g_s groups 0-1)
#define ES_F (64 * ESTR)
#define VS_F (64 * XSTR)
#define K3_SMEM ((4 * ES_F + 4 * VS_F + 256 + 16) * 4)

__global__ __launch_bounds__(256) void k3_attn(const float* __restrict__ x,
                                               const float* __restrict__ Wv) {
    extern __shared__ __align__(16) float sm[];
    float* es  = sm;
    float* vs  = sm + 4 * ES_F;
    float* Wvs = sm + 4 * ES_F + 4 * VS_F;
    float2* rbuf = reinterpret_cast<float2*>(Wvs + 256);

    const int tid = threadIdx.x;
    Wvs[tid] = Wv[tid];
    const int g = tid >> 6, s6 = tid & 63, qt = s6 >> 2, dt = s6 & 3;
    const int lane = tid & 31, wid = tid >> 5;
    const int kbase = (tid & 3) * 16;
    const int colA = (tid >> 2) ^ ((tid & 3) * 4);

    float moffA[16];
#pragma unroll
    for (int j4 = 0; j4 < 4; ++j4) {
        float4 m4 = *reinterpret_cast<const float4*>(&g_moff[tid * 16 + j4 * 4]);
        moffA[j4 * 4 + 0] = m4.x; moffA[j4 * 4 + 1] = m4.y;
        moffA[j4 * 4 + 2] = m4.z; moffA[j4 * 4 + 3] = m4.w;
    }
    __syncthreads();

    const int bB = blockIdx.x * 16;
    float4 sreg[2][4];
#pragma unroll
    for (int gg = 0; gg < 2; ++gg)
#pragma unroll
        for (int j4 = 0; j4 < 4; ++j4)
            sreg[gg][j4] = *reinterpret_cast<const float4*>(
                &g_s[(size_t)(bB + gg) * QK + tid * 16 + j4 * 4]);

    for (int it = 0; it < 4; ++it) {
        const int b0 = bB + it * 4;
#pragma unroll
        for (int gg = 0; gg < 4; ++gg) {
            const float* sb = g_s + (size_t)(b0 + gg) * QK + tid * 16;
            float* eg = es + gg * ES_F;
#pragma unroll
            for (int j4 = 0; j4 < 4; ++j4) {
                float4 sv = (gg < 2) ? sreg[gg][j4]
                                     : *reinterpret_cast<const float4*>(&sb[j4 * 4]);
                const int k0 = kbase + j4 * 4;
                eg[(k0 + 0) * ESTR + colA] = __expf(sv.x - moffA[j4 * 4 + 0]);
                eg[(k0 + 1) * ESTR + colA] = __expf(sv.y - moffA[j4 * 4 + 1]);
                eg[(k0 + 2) * ESTR + colA] = __expf(sv.z - moffA[j4 * 4 + 2]);
                eg[(k0 + 3) * ESTR + colA] = __expf(sv.w - moffA[j4 * 4 + 3]);
            }
        }
        if (it < 3) {
#pragma unroll
            for (int gg = 0; gg < 2; ++gg)
#pragma unroll
                for (int j4 = 0; j4 < 4; ++j4)
                    sreg[gg][j4] = *reinterpret_cast<const float4*>(
                        &g_s[(size_t)(b0 + 4 + gg) * QK + tid * 16 + j4 * 4]);
        }
        {
            const float* xb = x + (size_t)(b0 + g) * 1024 + s6 * 16;
            u64 va[8];
#pragma unroll
            for (int i = 0; i < 8; ++i) va[i] = 0ull;
#pragma unroll
            for (int c = 0; c < 4; ++c) {
                float4 x4 = *reinterpret_cast<const float4*>(&xb[c * 4]);
#pragma unroll
                for (int e = 0; e < 4; ++e) {
                    float xv = (e == 0) ? x4.x : (e == 1) ? x4.y : (e == 2) ? x4.z : x4.w;
                    u64 xp = pack2(xv);
                    const ulonglong2* wr =
                        reinterpret_cast<const ulonglong2*>(&Wvs[(c * 4 + e) * 16]);
                    fma2(va[0], xp, wr[0].x); fma2(va[1], xp, wr[0].y);
                    fma2(va[2], xp, wr[1].x); fma2(va[3], xp, wr[1].y);
                    fma2(va[4], xp, wr[2].x); fma2(va[5], xp, wr[2].y);
                    fma2(va[6], xp, wr[3].x); fma2(va[7], xp, wr[3].y);
                }
            }
            float* vrow = vs + g * VS_F + s6 * XSTR;
#pragma unroll
            for (int i = 0; i < 4; ++i) {
                ulonglong2 vv; vv.x = va[2 * i]; vv.y = va[2 * i + 1];
                *reinterpret_cast<ulonglong2*>(&vrow[i * 4]) = vv;
            }
        }
        __syncthreads();
        u64 acc[8];
#pragma unroll
        for (int i = 0; i < 8; ++i) acc[i] = 0ull;
        const float* eg = es + g * ES_F;
        const float* vg = vs + g * VS_F;
#pragma unroll
        for (int k = 0; k < 64; ++k) {
            const int col = (qt * 4) ^ ((k & 48) >> 2);
            float4 e4 = *reinterpret_cast<const float4*>(&eg[k * ESTR + col]);
            ulonglong2 v2 = *reinterpret_cast<const ulonglong2*>(&vg[k * XSTR + dt * 4]);
            u64 e0 = pack2(e4.x), e1 = pack2(e4.y), e2 = pack2(e4.z), e3 = pack2(e4.w);
            fma2(acc[0], e0, v2.x); fma2(acc[1], e0, v2.y);
            fma2(acc[2], e1, v2.x); fma2(acc[3], e1, v2.y);
            fma2(acc[4], e2, v2.x); fma2(acc[5], e2, v2.y);
            fma2(acc[6], e3, v2.x); fma2(acc[7], e3, v2.y);
        }
        const int b = b0 + g;
        float u[16];
        float ps = 0.f, pss = 0.f;
#pragma unroll
        for (int r = 0; r < 4; ++r) {
            float4 xr = *reinterpret_cast<const float4*>(
                &x[(size_t)b * 1024 + (qt * 4 + r) * 16 + dt * 4]);
            float2 lo = unpack2(acc[2 * r]), hi = unpack2(acc[2 * r + 1]);
            float u0 = xr.x + lo.x, u1 = xr.y + lo.y, u2 = xr.z + hi.x, u3 = xr.w + hi.y;
            u[r * 4 + 0] = u0; u[r * 4 + 1] = u1; u[r * 4 + 2] = u2; u[r * 4 + 3] = u3;
            ps += u0 + u1 + u2 + u3;
            pss = fmaf(u0, u0, fmaf(u1, u1, fmaf(u2, u2, fmaf(u3, u3, pss))));
        }
#pragma unroll
        for (int o = 16; o > 0; o >>= 1) {
            ps  += __shfl_down_sync(0xffffffffu, ps, o);
            pss += __shfl_down_sync(0xffffffffu, pss, o);
        }
        if (lane == 0) rbuf[wid] = make_float2(ps, pss);
        __syncthreads();
        float2 r0 = rbuf[g * 2], r1 = rbuf[g * 2 + 1];
        float mean = (r0.x + r1.x) * (1.f / 1024.f);
        float var  = (r0.y + r1.y) * (1.f / 1024.f) - mean * mean;
        float rstd = rsqrtf(var + 1e-5f);
#pragma unroll
        for (int r = 0; r < 4; ++r) {
            float4 o4 = make_float4((u[r * 4 + 0] - mean) * rstd,
                                    (u[r * 4 + 1] - mean) * rstd,
                                    (u[r * 4 + 2] - mean) * rstd,
                                    (u[r * 4 + 3] - mean) * rstd);
            *reinterpret_cast<float4*>(
                &g_u[(size_t)b * 1024 + (qt * 4 + r) * 16 + dt * 4]) = o4;
        }
        __syncthreads();
    }
}

// -------- k4   (verbatim R12: g_u prefetch)
__global__ __launch_bounds__(256) void k4_mlp(const float* __restrict__ W1,
                                              const float* __restrict__ b1,
                                              const float* __restrict__ W2,
                                              const float* __restrict__ b2,
                                              float* __restrict__ out) {
    const int tid = threadIdx.x;
    const int p = tid >> 2, ob = (tid & 3) << 2;
    const int lane = tid & 31, wid = tid >> 5;
    const int base = lane & ~3;
    ulonglong2 rw1[16], rw2[16];
#pragma unroll
    for (int i = 0; i < 16; ++i) {
        rw1[i] = *reinterpret_cast<const ulonglong2*>(&W1[p * 256 + i * 16 + ob]);
        rw2[i] = *reinterpret_cast<const ulonglong2*>(&W2[p * 256 + i * 16 + ob]);
    }
    float4 rb1 = *reinterpret_cast<const float4*>(&b1[p * 16 + ob]);
    float4 rb2 = *reinterpret_cast<const float4*>(&b2[p * 16 + ob]);
    __shared__ float2 rbuf[2][8];

    float4 pre = *reinterpret_cast<const float4*>(&g_u[(size_t)blockIdx.x * 1024 + tid * 4]);

    int parity = 0;
    for (int b = blockIdx.x; b < NB; b += gridDim.x, parity ^= 1) {
        float4 xv = pre;
        if (b + (int)gridDim.x < NB)
            pre = *reinterpret_cast<const float4*>(
                &g_u[(size_t)(b + gridDim.x) * 1024 + tid * 4]);
        float row[16];
#pragma unroll
        for (int c = 0; c < 4; ++c) {
            row[c * 4 + 0] = __shfl_sync(0xffffffffu, xv.x, base + c);
            row[c * 4 + 1] = __shfl_sync(0xffffffffu, xv.y, base + c);
            row[c * 4 + 2] = __shfl_sync(0xffffffffu, xv.z, base + c);
            row[c * 4 + 3] = __shfl_sync(0xffffffffu, xv.w, base + c);
        }
        u64 h0 = pack2b(rb1.x, rb1.y), h1 = pack2b(rb1.z, rb1.w);
#pragma unroll
        for (int i = 0; i < 16; ++i) {
            u64 xp = pack2(row[i]);
            fma2(h0, xp, rw1[i].x); fma2(h1, xp, rw1[i].y);
        }
        float2 hA = unpack2(h0), hB = unpack2(h1);
        float4 hv = make_float4(fmaxf(hA.x, 0.f), fmaxf(hA.y, 0.f),
                                fmaxf(hB.x, 0.f), fmaxf(hB.y, 0.f));
#pragma unroll
        for (int c = 0; c < 4; ++c) {
            row[c * 4 + 0] = __shfl_sync(0xffffffffu, hv.x, base + c);
            row[c * 4 + 1] = __shfl_sync(0xffffffffu, hv.y, base + c);
            row[c * 4 + 2] = __shfl_sync(0xffffffffu, hv.z, base + c);
            row[c * 4 + 3] = __shfl_sync(0xffffffffu, hv.w, base + c);
        }
        u64 g0 = pack2b(rb2.x, rb2.y), g1 = pack2b(rb2.z, rb2.w);
#pragma unroll
        for (int i = 0; i < 16; ++i) {
            u64 hp = pack2(row[i]);
            fma2(g0, hp, rw2[i].x); fma2(g1, hp, rw2[i].y);
        }
        float2 gA = unpack2(g0), gB = unpack2(g1);
        float4 u;
        u.x = fmaxf(gA.x, 0.f) + xv.x;
        u.y = fmaxf(gA.y, 0.f) + xv.y;
        u.z = fmaxf(gB.x, 0.f) + xv.z;
        u.w = fmaxf(gB.y, 0.f) + xv.w;

        float ps = u.x + u.y + u.z + u.w;
        float pss = fmaf(u.x, u.x, fmaf(u.y, u.y, fmaf(u.z, u.z, u.w * u.w)));
#pragma unroll
        for (int o = 16; o > 0; o >>= 1) {
            ps  += __shfl_down_sync(0xffffffffu, ps, o);
            pss += __shfl_down_sync(0xffffffffu, pss, o);
        }
        if (lane == 0) rbuf[parity][wid] = make_float2(ps, pss);
        __syncthreads();
        float s = 0.f, ss = 0.f;
#pragma unroll
        for (int w = 0; w < 8; ++w) {
            float2 t = rbuf[parity][w];
            s += t.x; ss += t.y;
        }
        float mean = s * (1.f / 1024.f);
        float var  = ss * (1.f / 1024.f) - mean * mean;
        float rstd = rsqrtf(var + 1e-5f);
        float4 o4 = make_float4((u.x - mean) * rstd, (u.y - mean) * rstd,
                                (u.z - mean) * rstd, (u.w - mean) * rstd);
        *reinterpret_cast<float4*>(&out[(size_t)b * 1024 + tid * 4]) = o4;
    }
}

extern "C" void kernel_launch(void* const* d_in, const int* in_sizes, int n_in,
                              void* d_out, int out_size) {
    const float* x  = (const float*)d_in[0];
    const float* Wq = (const float*)d_in[1];
    const float* Wk = (const float*)d_in[2];
    const float* Wv = (const float*)d_in[3];
    const float* W1 = (const float*)d_in[4];
    const float* b1 = (const float*)d_in[5];
    const float* W2 = (const float*)d_in[6];
    const float* b2 = (const float*)d_in[7];
    float* out = (float*)d_out;

    cudaFuncSetAttribute(k3_attn, cudaFuncAttributeMaxDynamicSharedMemorySize, K3_SMEM);

    k0_prep<<<1, 256>>>(Wq, Wk);
    k1_maxsum<<<NBLK1, 256>>>(x);
    k2a_reduce<<<16 * NCHUNK, 256>>>();
    k2b_reduce<<<QK / 256, 256>>>();
    k3_attn<<<2048, 256, K3_SMEM>>>(x, Wv);
    k4_mlp<<<2048, 256>>>(W1, b1, W2, b2, out);
}

// round 14
// speedup vs baseline: 1.0058x; 1.0058x over previous
#include <cuda_runtime.h>

#define NB    32768
#define QK    4096
#define NBLK1 1024
#define XSTR  20
#define ESTR  68
#define NCHUNK 16
#define PPERCH (NBLK1 / NCHUNK)

typedef unsigned long long u64;

__device__ float g_M[256];
__device__ float g_pm[(size_t)NBLK1 * QK];
__device__ float g_ps[(size_t)NBLK1 * QK];
__device__ float g_pm2[(size_t)NCHUNK * QK];
__device__ float g_ps2[(size_t)NCHUNK * QK];
__device__ float g_moff[QK];
__device__ float g_s[(size_t)NB * QK];    // scores, linear [b][q*64+k]
__device__ float g_u[(size_t)NB * 1024];

// ---- packed fp32x2 helpers ----
__device__ __forceinline__ void fma2(u64 &acc, u64 a, u64 b) {
    asm("fma.rn.f32x2 %0, %1, %2, %0;" : "+l"(acc) : "l"(a), "l"(b));
}
__device__ __forceinline__ u64 pack2(float x) {
    u64 r; asm("mov.b64 %0, {%1, %1};" : "=l"(r) : "f"(x)); return r;
}
__device__ __forceinline__ u64 pack2b(float x, float y) {
    u64 r; asm("mov.b64 %0, {%1, %2};" : "=l"(r) : "f"(x), "f"(y)); return r;
}
__device__ __forceinline__ float2 unpack2(u64 a) {
    float2 f; asm("mov.b64 {%0, %1}, %2;" : "=f"(f.x), "=f"(f.y) : "l"(a)); return f;
}

// -------- k0: M = Wq @ Wk^T / 3   (verbatim R12)
__global__ void k0_prep(const float* __restrict__ Wq, const float* __restrict__ Wk) {
    int t = threadIdx.x, i = t >> 4, j = t & 15;
    float a = 0.f;
#pragma unroll
    for (int o = 0; o < 16; ++o) a += Wq[i * 16 + o] * Wk[j * 16 + o];
    g_M[t] = a * (1.0f / 3.0f);
}

// -------- k1: REVERTED to R12 verbatim (reg-resident M, no launch-bounds min)
__global__ __launch_bounds__(256) void k1_maxsum(const float* __restrict__ x) {
    __shared__ __align__(16) float xs[2][64 * XSTR];
    __shared__ __align__(16) float ts[2][64 * XSTR];
    const int tid = threadIdx.x;
    const int ty = tid >> 4, tx = tid & 15;
    const int tq = tid >> 2, tc4 = (tid & 3) << 2;
    const int base = (tid & 31) & ~3;

    ulonglong2 rM[16];
#pragma unroll
    for (int d = 0; d < 16; ++d)
        rM[d] = *reinterpret_cast<const ulonglong2*>(&g_M[d * 16 + tc4]);

    float rm[16], rs[16];
#pragma unroll
    for (int j = 0; j < 16; ++j) { rm[j] = -1e30f; rs[j] = 0.f; }

    float4 pre = *reinterpret_cast<const float4*>(&x[(size_t)blockIdx.x * 1024 + tid * 4]);

    for (int it = 0; it < NB / NBLK1; ++it) {
        const int buf = it & 1;
        const int b = blockIdx.x + it * NBLK1;
        *reinterpret_cast<float4*>(&xs[buf][tq * XSTR + tc4]) = pre;
        float xrow[16];
#pragma unroll
        for (int c = 0; c < 4; ++c) {
            xrow[c * 4 + 0] = __shfl_sync(0xffffffffu, pre.x, base + c);
            xrow[c * 4 + 1] = __shfl_sync(0xffffffffu, pre.y, base + c);
            xrow[c * 4 + 2] = __shfl_sync(0xffffffffu, pre.z, base + c);
            xrow[c * 4 + 3] = __shfl_sync(0xffffffffu, pre.w, base + c);
        }
        {
            u64 t0 = 0, t1 = 0;
#pragma unroll
            for (int d = 0; d < 16; ++d) {
                u64 xp = pack2(xrow[d]);
                fma2(t0, xp, rM[d].x); fma2(t1, xp, rM[d].y);
            }
            ulonglong2 tv; tv.x = t0; tv.y = t1;
            *reinterpret_cast<ulonglong2*>(&ts[buf][tq * XSTR + tc4]) = tv;
        }
        if (it + 1 < NB / NBLK1)
            pre = *reinterpret_cast<const float4*>(
                &x[(size_t)(blockIdx.x + (it + 1) * NBLK1) * 1024 + tid * 4]);
        __syncthreads();
        u64 acc[16];
#pragma unroll
        for (int j = 0; j < 16; ++j) acc[j] = 0ull;
#pragma unroll
        for (int d4 = 0; d4 < 4; ++d4) {
            ulonglong2 a[4], bb[4];
#pragma unroll
            for (int r = 0; r < 4; ++r)
                a[r] = *reinterpret_cast<const ulonglong2*>(&ts[buf][(ty + 16 * r) * XSTR + d4 * 4]);
#pragma unroll
            for (int c = 0; c < 4; ++c)
                bb[c] = *reinterpret_cast<const ulonglong2*>(&xs[buf][(4 * tx + c) * XSTR + d4 * 4]);
#pragma unroll
            for (int r = 0; r < 4; ++r)
#pragma unroll
                for (int c = 0; c < 4; ++c) {
                    fma2(acc[r * 4 + c], a[r].x, bb[c].x);
                    fma2(acc[r * 4 + c], a[r].y, bb[c].y);
                }
        }
        float sv[16];
#pragma unroll
        for (int j = 0; j < 16; ++j) {
            float2 p2 = unpack2(acc[j]);
            sv[j] = p2.x + p2.y;
        }
#pragma unroll
        for (int j = 0; j < 16; ++j) {
            float v = sv[j];
            float d = v - rm[j];
            float e = __expf(fminf(d, -d));
            rs[j] = (d > 0.f) ? fmaf(rs[j], e, 1.f) : (rs[j] + e);
            rm[j] = fmaxf(rm[j], v);
        }
        float* sb = g_s + (size_t)b * QK;
#pragma unroll
        for (int r = 0; r < 4; ++r)
            *reinterpret_cast<float4*>(&sb[(ty + 16 * r) * 64 + 4 * tx]) =
                make_float4(sv[r * 4 + 0], sv[r * 4 + 1], sv[r * 4 + 2], sv[r * 4 + 3]);
    }
#pragma unroll
    for (int j = 0; j < 16; ++j) {
        int q = ty + 16 * (j >> 2), k = 4 * tx + (j & 3);
        g_pm[(size_t)blockIdx.x * QK + q * 64 + k] = rm[j];
        g_ps[(size_t)blockIdx.x * QK + q * 64 + k] = rs[j];
    }
}

// -------- k2a   (verbatim R12)
__global__ __launch_bounds__(256) void k2a_reduce(void) {
    const int posblk = blockIdx.x & 15;
    const int pchunk = blockIdx.x >> 4;
    const int pos = posblk * 256 + threadIdx.x;
    const int p0 = pchunk * PPERCH;

    float m = -1e30f, S = 0.f;
#pragma unroll 1
    for (int pp = 0; pp < PPERCH; pp += 4) {
        float ml[4], sl[4];
#pragma unroll
        for (int i = 0; i < 4; ++i) {
            ml[i] = g_pm[(size_t)(p0 + pp + i) * QK + pos];
            sl[i] = g_ps[(size_t)(p0 + pp + i) * QK + pos];
        }
#pragma unroll
        for (int i = 0; i < 4; ++i) {
            if (ml[i] > m) { S = fmaf(S, __expf(m - ml[i]), sl[i]); m = ml[i]; }
            else           { S = fmaf(sl[i], __expf(ml[i] - m), S); }
        }
    }
    g_pm2[(size_t)pchunk * QK + pos] = m;
    g_ps2[(size_t)pchunk * QK + pos] = S;
}

// -------- k2b   (verbatim R12)
__global__ __launch_bounds__(256) void k2b_reduce(void) {
    const int pos = blockIdx.x * 256 + threadIdx.x;
    float m = -1e30f, S = 0.f;
#pragma unroll
    for (int c = 0; c < NCHUNK; ++c) {
        float mc = g_pm2[(size_t)c * QK + pos];
        float sc = g_ps2[(size_t)c * QK + pos];
        if (mc > m) { S = fmaf(S, __expf(m - mc), sc); m = mc; }
        else        { S = fmaf(sc, __expf(mc - m), S); }
    }
    g_moff[pos] = m + __logf(S);
}

// -------- k3   (verbatim R12) + carveout attribute set host-side
#define ES_F (64 * ESTR)
#define VS_F (64 * XSTR)
#define K3_SMEM ((4 * ES_F + 4 * VS_F + 256 + 16) * 4)

__global__ __launch_bounds__(256) void k3_attn(const float* __restrict__ x,
                                               const float* __restrict__ Wv) {
    extern __shared__ __align__(16) float sm[];
    float* es  = sm;
    float* vs  = sm + 4 * ES_F;
    float* Wvs = sm + 4 * ES_F + 4 * VS_F;
    float2* rbuf = reinterpret_cast<float2*>(Wvs + 256);

    const int tid = threadIdx.x;
    Wvs[tid] = Wv[tid];
    const int g = tid >> 6, s6 = tid & 63, qt = s6 >> 2, dt = s6 & 3;
    const int lane = tid & 31, wid = tid >> 5;
    const int kbase = (tid & 3) * 16;
    const int colA = (tid >> 2) ^ ((tid & 3) * 4);

    float moffA[16];
#pragma unroll
    for (int j4 = 0; j4 < 4; ++j4) {
        float4 m4 = *reinterpret_cast<const float4*>(&g_moff[tid * 16 + j4 * 4]);
        moffA[j4 * 4 + 0] = m4.x; moffA[j4 * 4 + 1] = m4.y;
        moffA[j4 * 4 + 2] = m4.z; moffA[j4 * 4 + 3] = m4.w;
    }
    __syncthreads();

    const int bB = blockIdx.x * 16;
    float4 sreg[2][4];
#pragma unroll
    for (int gg = 0; gg < 2; ++gg)
#pragma unroll
        for (int j4 = 0; j4 < 4; ++j4)
            sreg[gg][j4] = *reinterpret_cast<const float4*>(
                &g_s[(size_t)(bB + gg) * QK + tid * 16 + j4 * 4]);

    for (int it = 0; it < 4; ++it) {
        const int b0 = bB + it * 4;
#pragma unroll
        for (int gg = 0; gg < 4; ++gg) {
            const float* sb = g_s + (size_t)(b0 + gg) * QK + tid * 16;
            float* eg = es + gg * ES_F;
#pragma unroll
            for (int j4 = 0; j4 < 4; ++j4) {
                float4 sv = (gg < 2) ? sreg[gg][j4]
                                     : *reinterpret_cast<const float4*>(&sb[j4 * 4]);
                const int k0 = kbase + j4 * 4;
                eg[(k0 + 0) * ESTR + colA] = __expf(sv.x - moffA[j4 * 4 + 0]);
                eg[(k0 + 1) * ESTR + colA] = __expf(sv.y - moffA[j4 * 4 + 1]);
                eg[(k0 + 2) * ESTR + colA] = __expf(sv.z - moffA[j4 * 4 + 2]);
                eg[(k0 + 3) * ESTR + colA] = __expf(sv.w - moffA[j4 * 4 + 3]);
            }
        }
        if (it < 3) {
#pragma unroll
            for (int gg = 0; gg < 2; ++gg)
#pragma unroll
                for (int j4 = 0; j4 < 4; ++j4)
                    sreg[gg][j4] = *reinterpret_cast<const float4*>(
                        &g_s[(size_t)(b0 + 4 + gg) * QK + tid * 16 + j4 * 4]);
        }
        {
            const float* xb = x + (size_t)(b0 + g) * 1024 + s6 * 16;
            u64 va[8];
#pragma unroll
            for (int i = 0; i < 8; ++i) va[i] = 0ull;
#pragma unroll
            for (int c = 0; c < 4; ++c) {
                float4 x4 = *reinterpret_cast<const float4*>(&xb[c * 4]);
#pragma unroll
                for (int e = 0; e < 4; ++e) {
                    float xv = (e == 0) ? x4.x : (e == 1) ? x4.y : (e == 2) ? x4.z : x4.w;
                    u64 xp = pack2(xv);
                    const ulonglong2* wr =
                        reinterpret_cast<const ulonglong2*>(&Wvs[(c * 4 + e) * 16]);
                    fma2(va[0], xp, wr[0].x); fma2(va[1], xp, wr[0].y);
                    fma2(va[2], xp, wr[1].x); fma2(va[3], xp, wr[1].y);
                    fma2(va[4], xp, wr[2].x); fma2(va[5], xp, wr[2].y);
                    fma2(va[6], xp, wr[3].x); fma2(va[7], xp, wr[3].y);
                }
            }
            float* vrow = vs + g * VS_F + s6 * XSTR;
#pragma unroll
            for (int i = 0; i < 4; ++i) {
                ulonglong2 vv; vv.x = va[2 * i]; vv.y = va[2 * i + 1];
                *reinterpret_cast<ulonglong2*>(&vrow[i * 4]) = vv;
            }
        }
        __syncthreads();
        u64 acc[8];
#pragma unroll
        for (int i = 0; i < 8; ++i) acc[i] = 0ull;
        const float* eg = es + g * ES_F;
        const float* vg = vs + g * VS_F;
#pragma unroll
        for (int k = 0; k < 64; ++k) {
            const int col = (qt * 4) ^ ((k & 48) >> 2);
            float4 e4 = *reinterpret_cast<const float4*>(&eg[k * ESTR + col]);
            ulonglong2 v2 = *reinterpret_cast<const ulonglong2*>(&vg[k * XSTR + dt * 4]);
            u64 e0 = pack2(e4.x), e1 = pack2(e4.y), e2 = pack2(e4.z), e3 = pack2(e4.w);
            fma2(acc[0], e0, v2.x); fma2(acc[1], e0, v2.y);
            fma2(acc[2], e1, v2.x); fma2(acc[3], e1, v2.y);
            fma2(acc[4], e2, v2.x); fma2(acc[5], e2, v2.y);
            fma2(acc[6], e3, v2.x); fma2(acc[7], e3, v2.y);
        }
        const int b = b0 + g;
        float u[16];
        float ps = 0.f, pss = 0.f;
#pragma unroll
        for (int r = 0; r < 4; ++r) {
            float4 xr = *reinterpret_cast<const float4*>(
                &x[(size_t)b * 1024 + (qt * 4 + r) * 16 + dt * 4]);
            float2 lo = unpack2(acc[2 * r]), hi = unpack2(acc[2 * r + 1]);
            float u0 = xr.x + lo.x, u1 = xr.y + lo.y, u2 = xr.z + hi.x, u3 = xr.w + hi.y;
            u[r * 4 + 0] = u0; u[r * 4 + 1] = u1; u[r * 4 + 2] = u2; u[r * 4 + 3] = u3;
            ps += u0 + u1 + u2 + u3;
            pss = fmaf(u0, u0, fmaf(u1, u1, fmaf(u2, u2, fmaf(u3, u3, pss))));
        }
#pragma unroll
        for (int o = 16; o > 0; o >>= 1) {
            ps  += __shfl_down_sync(0xffffffffu, ps, o);
            pss += __shfl_down_sync(0xffffffffu, pss, o);
        }
        if (lane == 0) rbuf[wid] = make_float2(ps, pss);
        __syncthreads();
        float2 r0 = rbuf[g * 2], r1 = rbuf[g * 2 + 1];
        float mean = (r0.x + r1.x) * (1.f / 1024.f);
        float var  = (r0.y + r1.y) * (1.f / 1024.f) - mean * mean;
        float rstd = rsqrtf(var + 1e-5f);
#pragma unroll
        for (int r = 0; r < 4; ++r) {
            float4 o4 = make_float4((u[r * 4 + 0] - mean) * rstd,
                                    (u[r * 4 + 1] - mean) * rstd,
                                    (u[r * 4 + 2] - mean) * rstd,
                                    (u[r * 4 + 3] - mean) * rstd);
            *reinterpret_cast<float4*>(
                &g_u[(size_t)b * 1024 + (qt * 4 + r) * 16 + dt * 4]) = o4;
        }
        __syncthreads();
    }
}

// -------- k4   (verbatim R12: g_u prefetch)
__global__ __launch_bounds__(256) void k4_mlp(const float* __restrict__ W1,
                                              const float* __restrict__ b1,
                                              const float* __restrict__ W2,
                                              const float* __restrict__ b2,
                                              float* __restrict__ out) {
    const int tid = threadIdx.x;
    const int p = tid >> 2, ob = (tid & 3) << 2;
    const int lane = tid & 31, wid = tid >> 5;
    const int base = lane & ~3;
    ulonglong2 rw1[16], rw2[16];
#pragma unroll
    for (int i = 0; i < 16; ++i) {
        rw1[i] = *reinterpret_cast<const ulonglong2*>(&W1[p * 256 + i * 16 + ob]);
        rw2[i] = *reinterpret_cast<const ulonglong2*>(&W2[p * 256 + i * 16 + ob]);
    }
    float4 rb1 = *reinterpret_cast<const float4*>(&b1[p * 16 + ob]);
    float4 rb2 = *reinterpret_cast<const float4*>(&b2[p * 16 + ob]);
    __shared__ float2 rbuf[2][8];

    float4 pre = *reinterpret_cast<const float4*>(&g_u[(size_t)blockIdx.x * 1024 + tid * 4]);

    int parity = 0;
    for (int b = blockIdx.x; b < NB; b += gridDim.x, parity ^= 1) {
        float4 xv = pre;
        if (b + (int)gridDim.x < NB)
            pre = *reinterpret_cast<const float4*>(
                &g_u[(size_t)(b + gridDim.x) * 1024 + tid * 4]);
        float row[16];
#pragma unroll
        for (int c = 0; c < 4; ++c) {
            row[c * 4 + 0] = __shfl_sync(0xffffffffu, xv.x, base + c);
            row[c * 4 + 1] = __shfl_sync(0xffffffffu, xv.y, base + c);
            row[c * 4 + 2] = __shfl_sync(0xffffffffu, xv.z, base + c);
            row[c * 4 + 3] = __shfl_sync(0xffffffffu, xv.w, base + c);
        }
        u64 h0 = pack2b(rb1.x, rb1.y), h1 = pack2b(rb1.z, rb1.w);
#pragma unroll
        for (int i = 0; i < 16; ++i) {
            u64 xp = pack2(row[i]);
            fma2(h0, xp, rw1[i].x); fma2(h1, xp, rw1[i].y);
        }
        float2 hA = unpack2(h0), hB = unpack2(h1);
        float4 hv = make_float4(fmaxf(hA.x, 0.f), fmaxf(hA.y, 0.f),
                                fmaxf(hB.x, 0.f), fmaxf(hB.y, 0.f));
#pragma unroll
        for (int c = 0; c < 4; ++c) {
            row[c * 4 + 0] = __shfl_sync(0xffffffffu, hv.x, base + c);
            row[c * 4 + 1] = __shfl_sync(0xffffffffu, hv.y, base + c);
            row[c * 4 + 2] = __shfl_sync(0xffffffffu, hv.z, base + c);
            row[c * 4 + 3] = __shfl_sync(0xffffffffu, hv.w, base + c);
        }
        u64 g0 = pack2b(rb2.x, rb2.y), g1 = pack2b(rb2.z, rb2.w);
#pragma unroll
        for (int i = 0; i < 16; ++i) {
            u64 hp = pack2(row[i]);
            fma2(g0, hp, rw2[i].x); fma2(g1, hp, rw2[i].y);
        }
        float2 gA = unpack2(g0), gB = unpack2(g1);
        float4 u;
        u.x = fmaxf(gA.x, 0.f) + xv.x;
        u.y = fmaxf(gA.y, 0.f) + xv.y;
        u.z = fmaxf(gB.x, 0.f) + xv.z;
        u.w = fmaxf(gB.y, 0.f) + xv.w;

        float ps = u.x + u.y + u.z + u.w;
        float pss = fmaf(u.x, u.x, fmaf(u.y, u.y, fmaf(u.z, u.z, u.w * u.w)));
#pragma unroll
        for (int o = 16; o > 0; o >>= 1) {
            ps  += __shfl_down_sync(0xffffffffu, ps, o);
            pss += __shfl_down_sync(0xffffffffu, pss, o);
        }
        if (lane == 0) rbuf[parity][wid] = make_float2(ps, pss);
        __syncthreads();
        float s = 0.f, ss = 0.f;
#pragma unroll
        for (int w = 0; w < 8; ++w) {
            float2 t = rbuf[parity][w];
            s += t.x; ss += t.y;
        }
        float mean = s * (1.f / 1024.f);
        float var  = ss * (1.f / 1024.f) - mean * mean;
        float rstd = rsqrtf(var + 1e-5f);
        float4 o4 = make_float4((u.x - mean) * rstd, (u.y - mean) * rstd,
                                (u.z - mean) * rstd, (u.w - mean) * rstd);
        *reinterpret_cast<float4*>(&out[(size_t)b * 1024 + tid * 4]) = o4;
    }
}

extern "C" void kernel_launch(void* const* d_in, const int* in_sizes, int n_in,
                              void* d_out, int out_size) {
    const float* x  = (const float*)d_in[0];
    const float* Wq = (const float*)d_in[1];
    const float* Wk = (const float*)d_in[2];
    const float* Wv = (const float*)d_in[3];
    const float* W1 = (const float*)d_in[4];
    const float* b1 = (const float*)d_in[5];
    const float* W2 = (const float*)d_in[6];
    const float* b2 = (const float*)d_in[7];
    float* out = (float*)d_out;

    cudaFuncSetAttribute(k3_attn, cudaFuncAttributeMaxDynamicSharedMemorySize, K3_SMEM);
    // Raise the per-SM shared-memory carveout so TWO 91KB blocks can co-reside
    // (default carveout caps the pool below 182KB -> 1 block/SM, occ ~25%).
    cudaFuncSetAttribute(k3_attn, cudaFuncAttributePreferredSharedMemoryCarveout, 100);

    k0_prep<<<1, 256>>>(Wq, Wk);
    k1_maxsum<<<NBLK1, 256>>>(x);
    k2a_reduce<<<16 * NCHUNK, 256>>>();
    k2b_reduce<<<QK / 256, 256>>>();
    k3_attn<<<2048, 256, K3_SMEM>>>(x, Wv);
    k4_mlp<<<2048, 256>>>(W1, b1, W2, b2, out);
}

// round 15
// speedup vs baseline: 1.1644x; 1.1577x over previous
#include <cuda_runtime.h>

#define NB    32768
#define QK    4096
#define NBLK1 1024
#define XSTR  20
#define ESTR  68
#define NCHUNK 16
#define PPERCH (NBLK1 / NCHUNK)

// skewed row offset for k1 tiles: 20 floats/row + 4-float skew every 4 rows
// -> row stride for rows 4tx+c becomes 84 words (== 20 mod 32 banks): 2-way
//    conflicts instead of 8-way, and 16B alignment is preserved.
#define ROFF(r) ((r) * 20 + ((r) & ~3))
#define K1_TILE 1360

typedef unsigned long long u64;

__device__ float g_M[256];
__device__ float g_pm[(size_t)NBLK1 * QK];
__device__ float g_ps[(size_t)NBLK1 * QK];
__device__ float g_pm2[(size_t)NCHUNK * QK];
__device__ float g_ps2[(size_t)NCHUNK * QK];
__device__ float g_moff[QK];
__device__ float g_s[(size_t)NB * QK];    // scores, linear [b][q*64+k]
__device__ float g_u[(size_t)NB * 1024];

// ---- packed fp32x2 helpers ----
__device__ __forceinline__ void fma2(u64 &acc, u64 a, u64 b) {
    asm("fma.rn.f32x2 %0, %1, %2, %0;" : "+l"(acc) : "l"(a), "l"(b));
}
__device__ __forceinline__ u64 pack2(float x) {
    u64 r; asm("mov.b64 %0, {%1, %1};" : "=l"(r) : "f"(x)); return r;
}
__device__ __forceinline__ u64 pack2b(float x, float y) {
    u64 r; asm("mov.b64 %0, {%1, %2};" : "=l"(r) : "f"(x), "f"(y)); return r;
}
__device__ __forceinline__ float2 unpack2(u64 a) {
    float2 f; asm("mov.b64 {%0, %1}, %2;" : "=f"(f.x), "=f"(f.y) : "l"(a)); return f;
}

// -------- k0: M = Wq @ Wk^T / 3   (verbatim R12)
__global__ void k0_prep(const float* __restrict__ Wq, const float* __restrict__ Wk) {
    int t = threadIdx.x, i = t >> 4, j = t & 15;
    float a = 0.f;
#pragma unroll
    for (int o = 0; o < 16; ++o) a += Wq[i * 16 + o] * Wk[j * 16 + o];
    g_M[t] = a * (1.0f / 3.0f);
}

// -------- k1: R12 structure + skewed smem rows (bank-conflict fix)
__global__ __launch_bounds__(256) void k1_maxsum(const float* __restrict__ x) {
    __shared__ __align__(16) float xs[2][K1_TILE];
    __shared__ __align__(16) float ts[2][K1_TILE];
    const int tid = threadIdx.x;
    const int ty = tid >> 4, tx = tid & 15;
    const int tq = tid >> 2, tc4 = (tid & 3) << 2;
    const int base = (tid & 31) & ~3;

    ulonglong2 rM[16];
#pragma unroll
    for (int d = 0; d < 16; ++d)
        rM[d] = *reinterpret_cast<const ulonglong2*>(&g_M[d * 16 + tc4]);

    float rm[16], rs[16];
#pragma unroll
    for (int j = 0; j < 16; ++j) { rm[j] = -1e30f; rs[j] = 0.f; }

    float4 pre = *reinterpret_cast<const float4*>(&x[(size_t)blockIdx.x * 1024 + tid * 4]);

    for (int it = 0; it < NB / NBLK1; ++it) {
        const int buf = it & 1;
        const int b = blockIdx.x + it * NBLK1;
        *reinterpret_cast<float4*>(&xs[buf][ROFF(tq) + tc4]) = pre;
        float xrow[16];
#pragma unroll
        for (int c = 0; c < 4; ++c) {
            xrow[c * 4 + 0] = __shfl_sync(0xffffffffu, pre.x, base + c);
            xrow[c * 4 + 1] = __shfl_sync(0xffffffffu, pre.y, base + c);
            xrow[c * 4 + 2] = __shfl_sync(0xffffffffu, pre.z, base + c);
            xrow[c * 4 + 3] = __shfl_sync(0xffffffffu, pre.w, base + c);
        }
        {
            u64 t0 = 0, t1 = 0;
#pragma unroll
            for (int d = 0; d < 16; ++d) {
                u64 xp = pack2(xrow[d]);
                fma2(t0, xp, rM[d].x); fma2(t1, xp, rM[d].y);
            }
            ulonglong2 tv; tv.x = t0; tv.y = t1;
            *reinterpret_cast<ulonglong2*>(&ts[buf][ROFF(tq) + tc4]) = tv;
        }
        if (it + 1 < NB / NBLK1)
            pre = *reinterpret_cast<const float4*>(
                &x[(size_t)(blockIdx.x + (it + 1) * NBLK1) * 1024 + tid * 4]);
        __syncthreads();
        u64 acc[16];
#pragma unroll
        for (int j = 0; j < 16; ++j) acc[j] = 0ull;
#pragma unroll
        for (int d4 = 0; d4 < 4; ++d4) {
            ulonglong2 a[4], bb[4];
#pragma unroll
            for (int r = 0; r < 4; ++r)
                a[r] = *reinterpret_cast<const ulonglong2*>(&ts[buf][ROFF(ty + 16 * r) + d4 * 4]);
#pragma unroll
            for (int c = 0; c < 4; ++c)
                bb[c] = *reinterpret_cast<const ulonglong2*>(&xs[buf][ROFF(4 * tx + c) + d4 * 4]);
#pragma unroll
            for (int r = 0; r < 4; ++r)
#pragma unroll
                for (int c = 0; c < 4; ++c) {
                    fma2(acc[r * 4 + c], a[r].x, bb[c].x);
                    fma2(acc[r * 4 + c], a[r].y, bb[c].y);
                }
        }
        float sv[16];
#pragma unroll
        for (int j = 0; j < 16; ++j) {
            float2 p2 = unpack2(acc[j]);
            sv[j] = p2.x + p2.y;
        }
#pragma unroll
        for (int j = 0; j < 16; ++j) {
            float v = sv[j];
            float d = v - rm[j];
            float e = __expf(fminf(d, -d));
            rs[j] = (d > 0.f) ? fmaf(rs[j], e, 1.f) : (rs[j] + e);
            rm[j] = fmaxf(rm[j], v);
        }
        float* sb = g_s + (size_t)b * QK;
#pragma unroll
        for (int r = 0; r < 4; ++r)
            *reinterpret_cast<float4*>(&sb[(ty + 16 * r) * 64 + 4 * tx]) =
                make_float4(sv[r * 4 + 0], sv[r * 4 + 1], sv[r * 4 + 2], sv[r * 4 + 3]);
    }
#pragma unroll
    for (int j = 0; j < 16; ++j) {
        int q = ty + 16 * (j >> 2), k = 4 * tx + (j & 3);
        g_pm[(size_t)blockIdx.x * QK + q * 64 + k] = rm[j];
        g_ps[(size_t)blockIdx.x * QK + q * 64 + k] = rs[j];
    }
}

// -------- k2a   (verbatim R12)
__global__ __launch_bounds__(256) void k2a_reduce(void) {
    const int posblk = blockIdx.x & 15;
    const int pchunk = blockIdx.x >> 4;
    const int pos = posblk * 256 + threadIdx.x;
    const int p0 = pchunk * PPERCH;

    float m = -1e30f, S = 0.f;
#pragma unroll 1
    for (int pp = 0; pp < PPERCH; pp += 4) {
        float ml[4], sl[4];
#pragma unroll
        for (int i = 0; i < 4; ++i) {
            ml[i] = g_pm[(size_t)(p0 + pp + i) * QK + pos];
            sl[i] = g_ps[(size_t)(p0 + pp + i) * QK + pos];
        }
#pragma unroll
        for (int i = 0; i < 4; ++i) {
            if (ml[i] > m) { S = fmaf(S, __expf(m - ml[i]), sl[i]); m = ml[i]; }
            else           { S = fmaf(sl[i], __expf(ml[i] - m), S); }
        }
    }
    g_pm2[(size_t)pchunk * QK + pos] = m;
    g_ps2[(size_t)pchunk * QK + pos] = S;
}

// -------- k2b   (verbatim R12)
__global__ __launch_bounds__(256) void k2b_reduce(void) {
    const int pos = blockIdx.x * 256 + threadIdx.x;
    float m = -1e30f, S = 0.f;
#pragma unroll
    for (int c = 0; c < NCHUNK; ++c) {
        float mc = g_pm2[(size_t)c * QK + pos];
        float sc = g_ps2[(size_t)c * QK + pos];
        if (mc > m) { S = fmaf(S, __expf(m - mc), sc); m = mc; }
        else        { S = fmaf(sc, __expf(mc - m), S); }
    }
    g_moff[pos] = m + __logf(S);
}

// -------- k3   (verbatim R12: prefetch of g_s groups 0-1)
#define ES_F (64 * ESTR)
#define VS_F (64 * XSTR)
#define K3_SMEM ((4 * ES_F + 4 * VS_F + 256 + 16) * 4)

__global__ __launch_bounds__(256) void k3_attn(const float* __restrict__ x,
                                               const float* __restrict__ Wv) {
    extern __shared__ __align__(16) float sm[];
    float* es  = sm;
    float* vs  = sm + 4 * ES_F;
    float* Wvs = sm + 4 * ES_F + 4 * VS_F;
    float2* rbuf = reinterpret_cast<float2*>(Wvs + 256);

    const int tid = threadIdx.x;
    Wvs[tid] = Wv[tid];
    const int g = tid >> 6, s6 = tid & 63, qt = s6 >> 2, dt = s6 & 3;
    const int lane = tid & 31, wid = tid >> 5;
    const int kbase = (tid & 3) * 16;
    const int colA = (tid >> 2) ^ ((tid & 3) * 4);

    float moffA[16];
#pragma unroll
    for (int j4 = 0; j4 < 4; ++j4) {
        float4 m4 = *reinterpret_cast<const float4*>(&g_moff[tid * 16 + j4 * 4]);
        moffA[j4 * 4 + 0] = m4.x; moffA[j4 * 4 + 1] = m4.y;
        moffA[j4 * 4 + 2] = m4.z; moffA[j4 * 4 + 3] = m4.w;
    }
    __syncthreads();

    const int bB = blockIdx.x * 16;
    float4 sreg[2][4];
#pragma unroll
    for (int gg = 0; gg < 2; ++gg)
#pragma unroll
        for (int j4 = 0; j4 < 4; ++j4)
            sreg[gg][j4] = *reinterpret_cast<const float4*>(
                &g_s[(size_t)(bB + gg) * QK + tid * 16 + j4 * 4]);

    for (int it = 0; it < 4; ++it) {
        const int b0 = bB + it * 4;
#pragma unroll
        for (int gg = 0; gg < 4; ++gg) {
            const float* sb = g_s + (size_t)(b0 + gg) * QK + tid * 16;
            float* eg = es + gg * ES_F;
#pragma unroll
            for (int j4 = 0; j4 < 4; ++j4) {
                float4 sv = (gg < 2) ? sreg[gg][j4]
                                     : *reinterpret_cast<const float4*>(&sb[j4 * 4]);
                const int k0 = kbase + j4 * 4;
                eg[(k0 + 0) * ESTR + colA] = __expf(sv.x - moffA[j4 * 4 + 0]);
                eg[(k0 + 1) * ESTR + colA] = __expf(sv.y - moffA[j4 * 4 + 1]);
                eg[(k0 + 2) * ESTR + colA] = __expf(sv.z - moffA[j4 * 4 + 2]);
                eg[(k0 + 3) * ESTR + colA] = __expf(sv.w - moffA[j4 * 4 + 3]);
            }
        }
        if (it < 3) {
#pragma unroll
            for (int gg = 0; gg < 2; ++gg)
#pragma unroll
                for (int j4 = 0; j4 < 4; ++j4)
                    sreg[gg][j4] = *reinterpret_cast<const float4*>(
                        &g_s[(size_t)(b0 + 4 + gg) * QK + tid * 16 + j4 * 4]);
        }
        {
            const float* xb = x + (size_t)(b0 + g) * 1024 + s6 * 16;
            u64 va[8];
#pragma unroll
            for (int i = 0; i < 8; ++i) va[i] = 0ull;
#pragma unroll
            for (int c = 0; c < 4; ++c) {
                float4 x4 = *reinterpret_cast<const float4*>(&xb[c * 4]);
#pragma unroll
                for (int e = 0; e < 4; ++e) {
                    float xv = (e == 0) ? x4.x : (e == 1) ? x4.y : (e == 2) ? x4.z : x4.w;
                    u64 xp = pack2(xv);
                    const ulonglong2* wr =
                        reinterpret_cast<const ulonglong2*>(&Wvs[(c * 4 + e) * 16]);
                    fma2(va[0], xp, wr[0].x); fma2(va[1], xp, wr[0].y);
                    fma2(va[2], xp, wr[1].x); fma2(va[3], xp, wr[1].y);
                    fma2(va[4], xp, wr[2].x); fma2(va[5], xp, wr[2].y);
                    fma2(va[6], xp, wr[3].x); fma2(va[7], xp, wr[3].y);
                }
            }
            float* vrow = vs + g * VS_F + s6 * XSTR;
#pragma unroll
            for (int i = 0; i < 4; ++i) {
                ulonglong2 vv; vv.x = va[2 * i]; vv.y = va[2 * i + 1];
                *reinterpret_cast<ulonglong2*>(&vrow[i * 4]) = vv;
            }
        }
        __syncthreads();
        u64 acc[8];
#pragma unroll
        for (int i = 0; i < 8; ++i) acc[i] = 0ull;
        const float* eg = es + g * ES_F;
        const float* vg = vs + g * VS_F;
#pragma unroll
        for (int k = 0; k < 64; ++k) {
            const int col = (qt * 4) ^ ((k & 48) >> 2);
            float4 e4 = *reinterpret_cast<const float4*>(&eg[k * ESTR + col]);
            ulonglong2 v2 = *reinterpret_cast<const ulonglong2*>(&vg[k * XSTR + dt * 4]);
            u64 e0 = pack2(e4.x), e1 = pack2(e4.y), e2 = pack2(e4.z), e3 = pack2(e4.w);
            fma2(acc[0], e0, v2.x); fma2(acc[1], e0, v2.y);
            fma2(acc[2], e1, v2.x); fma2(acc[3], e1, v2.y);
            fma2(acc[4], e2, v2.x); fma2(acc[5], e2, v2.y);
            fma2(acc[6], e3, v2.x); fma2(acc[7], e3, v2.y);
        }
        const int b = b0 + g;
        float u[16];
        float ps = 0.f, pss = 0.f;
#pragma unroll
        for (int r = 0; r < 4; ++r) {
            float4 xr = *reinterpret_cast<const float4*>(
                &x[(size_t)b * 1024 + (qt * 4 + r) * 16 + dt * 4]);
            float2 lo = unpack2(acc[2 * r]), hi = unpack2(acc[2 * r + 1]);
            float u0 = xr.x + lo.x, u1 = xr.y + lo.y, u2 = xr.z + hi.x, u3 = xr.w + hi.y;
            u[r * 4 + 0] = u0; u[r * 4 + 1] = u1; u[r * 4 + 2] = u2; u[r * 4 + 3] = u3;
            ps += u0 + u1 + u2 + u3;
            pss = fmaf(u0, u0, fmaf(u1, u1, fmaf(u2, u2, fmaf(u3, u3, pss))));
        }
#pragma unroll
        for (int o = 16; o > 0; o >>= 1) {
            ps  += __shfl_down_sync(0xffffffffu, ps, o);
            pss += __shfl_down_sync(0xffffffffu, pss, o);
        }
        if (lane == 0) rbuf[wid] = make_float2(ps, pss);
        __syncthreads();
        float2 r0 = rbuf[g * 2], r1 = rbuf[g * 2 + 1];
        float mean = (r0.x + r1.x) * (1.f / 1024.f);
        float var  = (r0.y + r1.y) * (1.f / 1024.f) - mean * mean;
        float rstd = rsqrtf(var + 1e-5f);
#pragma unroll
        for (int r = 0; r < 4; ++r) {
            float4 o4 = make_float4((u[r * 4 + 0] - mean) * rstd,
                                    (u[r * 4 + 1] - mean) * rstd,
                                    (u[r * 4 + 2] - mean) * rstd,
                                    (u[r * 4 + 3] - mean) * rstd);
            *reinterpret_cast<float4*>(
                &g_u[(size_t)b * 1024 + (qt * 4 + r) * 16 + dt * 4]) = o4;
        }
        __syncthreads();
    }
}

// -------- k4   (verbatim R12: g_u prefetch)
__global__ __launch_bounds__(256) void k4_mlp(const float* __restrict__ W1,
                                              const float* __restrict__ b1,
                                              const float* __restrict__ W2,
                                              const float* __restrict__ b2,
                                              float* __restrict__ out) {
    const int tid = threadIdx.x;
    const int p = tid >> 2, ob = (tid & 3) << 2;
    const int lane = tid & 31, wid = tid >> 5;
    const int base = lane & ~3;
    ulonglong2 rw1[16], rw2[16];
#pragma unroll
    for (int i = 0; i < 16; ++i) {
        rw1[i] = *reinterpret_cast<const ulonglong2*>(&W1[p * 256 + i * 16 + ob]);
        rw2[i] = *reinterpret_cast<const ulonglong2*>(&W2[p * 256 + i * 16 + ob]);
    }
    float4 rb1 = *reinterpret_cast<const float4*>(&b1[p * 16 + ob]);
    float4 rb2 = *reinterpret_cast<const float4*>(&b2[p * 16 + ob]);
    __shared__ float2 rbuf[2][8];

    float4 pre = *reinterpret_cast<const float4*>(&g_u[(size_t)blockIdx.x * 1024 + tid * 4]);

    int parity = 0;
    for (int b = blockIdx.x; b < NB; b += gridDim.x, parity ^= 1) {
        float4 xv = pre;
        if (b + (int)gridDim.x < NB)
            pre = *reinterpret_cast<const float4*>(
                &g_u[(size_t)(b + gridDim.x) * 1024 + tid * 4]);
        float row[16];
#pragma unroll
        for (int c = 0; c < 4; ++c) {
            row[c * 4 + 0] = __shfl_sync(0xffffffffu, xv.x, base + c);
            row[c * 4 + 1] = __shfl_sync(0xffffffffu, xv.y, base + c);
            row[c * 4 + 2] = __shfl_sync(0xffffffffu, xv.z, base + c);
            row[c * 4 + 3] = __shfl_sync(0xffffffffu, xv.w, base + c);
        }
        u64 h0 = pack2b(rb1.x, rb1.y), h1 = pack2b(rb1.z, rb1.w);
#pragma unroll
        for (int i = 0; i < 16; ++i) {
            u64 xp = pack2(row[i]);
            fma2(h0, xp, rw1[i].x); fma2(h1, xp, rw1[i].y);
        }
        float2 hA = unpack2(h0), hB = unpack2(h1);
        float4 hv = make_float4(fmaxf(hA.x, 0.f), fmaxf(hA.y, 0.f),
                                fmaxf(hB.x, 0.f), fmaxf(hB.y, 0.f));
#pragma unroll
        for (int c = 0; c < 4; ++c) {
            row[c * 4 + 0] = __shfl_sync(0xffffffffu, hv.x, base + c);
            row[c * 4 + 1] = __shfl_sync(0xffffffffu, hv.y, base + c);
            row[c * 4 + 2] = __shfl_sync(0xffffffffu, hv.z, base + c);
            row[c * 4 + 3] = __shfl_sync(0xffffffffu, hv.w, base + c);
        }
        u64 g0 = pack2b(rb2.x, rb2.y), g1 = pack2b(rb2.z, rb2.w);
#pragma unroll
        for (int i = 0; i < 16; ++i) {
            u64 hp = pack2(row[i]);
            fma2(g0, hp, rw2[i].x); fma2(g1, hp, rw2[i].y);
        }
        float2 gA = unpack2(g0), gB = unpack2(g1);
        float4 u;
        u.x = fmaxf(gA.x, 0.f) + xv.x;
        u.y = fmaxf(gA.y, 0.f) + xv.y;
        u.z = fmaxf(gB.x, 0.f) + xv.z;
        u.w = fmaxf(gB.y, 0.f) + xv.w;

        float ps = u.x + u.y + u.z + u.w;
        float pss = fmaf(u.x, u.x, fmaf(u.y, u.y, fmaf(u.z, u.z, u.w * u.w)));
#pragma unroll
        for (int o = 16; o > 0; o >>= 1) {
            ps  += __shfl_down_sync(0xffffffffu, ps, o);
            pss += __shfl_down_sync(0xffffffffu, pss, o);
        }
        if (lane == 0) rbuf[parity][wid] = make_float2(ps, pss);
        __syncthreads();
        float s = 0.f, ss = 0.f;
#pragma unroll
        for (int w = 0; w < 8; ++w) {
            float2 t = rbuf[parity][w];
            s += t.x; ss += t.y;
        }
        float mean = s * (1.f / 1024.f);
        float var  = ss * (1.f / 1024.f) - mean * mean;
        float rstd = rsqrtf(var + 1e-5f);
        float4 o4 = make_float4((u.x - mean) * rstd, (u.y - mean) * rstd,
                                (u.z - mean) * rstd, (u.w - mean) * rstd);
        *reinterpret_cast<float4*>(&out[(size_t)b * 1024 + tid * 4]) = o4;
    }
}

extern "C" void kernel_launch(void* const* d_in, const int* in_sizes, int n_in,
                              void* d_out, int out_size) {
    const float* x  = (const float*)d_in[0];
    const float* Wq = (const float*)d_in[1];
    const float* Wk = (const float*)d_in[2];
    const float* Wv = (const float*)d_in[3];
    const float* W1 = (const float*)d_in[4];
    const float* b1 = (const float*)d_in[5];
    const float* W2 = (const float*)d_in[6];
    const float* b2 = (const float*)d_in[7];
    float* out = (float*)d_out;

    cudaFuncSetAttribute(k3_attn, cudaFuncAttributeMaxDynamicSharedMemorySize, K3_SMEM);

    k0_prep<<<1, 256>>>(Wq, Wk);
    k1_maxsum<<<NBLK1, 256>>>(x);
    k2a_reduce<<<16 * NCHUNK, 256>>>();
    k2b_reduce<<<QK / 256, 256>>>();
    k3_attn<<<2048, 256, K3_SMEM>>>(x, Wv);
    k4_mlp<<<2048, 256>>>(W1, b1, W2, b2, out);
}